// round 15
// baseline (speedup 1.0000x reference)
#include <cuda_runtime.h>
#include <cstdint>

#define D       256
#define L       50
#define BSZ     4096

// Weights prepacked as tf32 B-fragments: uint2 at [(kk*32 + nt)*32 + lane]
//   .x = tf32(W[nt*8 + lane/4][kk*8 + lane%4])
//   .y = tf32(W[nt*8 + lane/4][kk*8 + lane%4 + 4])
__device__ uint2 g_wp1[32 * 32 * 32];   // 256 KB
__device__ uint2 g_wp2[32 * 32 * 32];
// Gather outputs: 64 float4 channels per batch (8 MB total)
__device__ float4 g_tq [BSZ * (D / 4)];
__device__ float4 g_tsv[BSZ * (D / 4)];

__device__ __forceinline__ float fsigmoid(float x) {
    return 1.0f / (1.0f + __expf(-x));
}

__device__ __forceinline__ uint32_t f2tf32(float f) {
    uint32_t u;
    asm("cvt.rna.tf32.f32 %0, %1;" : "=r"(u) : "f"(f));
    return u;
}

// ------------- Kernel 1: ragged gather-sum (one block/batch) + weight repack -
__global__ void __launch_bounds__(256, 8) gather_kernel(
    const int*   __restrict__ acts_req,
    const int*   __restrict__ acts_slot,
    const int*   __restrict__ acts_val,
    const float* __restrict__ w1,
    const float* __restrict__ w2,
    const float* __restrict__ emb)
{
    __shared__ int idx[3 * L + 2];
    __shared__ __align__(16) float4 redq [4][D / 4];
    __shared__ __align__(16) float4 redsv[4][D / 4];

    const int b   = blockIdx.x;
    const int tid = threadIdx.x;

    // Fold weight repack+tf32 fragment packing into the first 256 blocks.
    // 256 blocks x 256 threads = 65536 = 2 matrices x 32kk x 32nt x 32 lanes.
    if (b < 256) {
        int id   = b * 256 + tid;
        int mtx  = id >> 15;
        int r    = id & 32767;
        int kk   = r >> 10;
        int nt   = (r >> 5) & 31;
        int lane = r & 31;
        int i = nt * 8 + (lane >> 2);
        int j = kk * 8 + (lane & 3);
        const float* w = mtx ? w2 : w1;
        uint2 frag;
        frag.x = f2tf32(w[i * D + j]);
        frag.y = f2tf32(w[i * D + j + 4]);
        (mtx ? g_wp2 : g_wp1)[(kk * 32 + nt) * 32 + lane] = frag;
    }

    if (tid < 3 * L) {
        int v;
        if      (tid < L)     v = acts_req [b * L + tid];
        else if (tid < 2 * L) v = acts_slot[b * L + (tid - L)];
        else                  v = acts_val [b * L + (tid - 2 * L)];
        idx[tid] = v;
    }
    __syncthreads();

    const float4* __restrict__ emb4 = (const float4*)emb;
    const int p    = tid >> 6;
    const int lane = tid & 63;

    float4 q0 = make_float4(0.f,0.f,0.f,0.f), q1 = q0, s0 = q0, s1 = q0;

    #pragma unroll
    for (int k = 0; k < 13; k++) {
        int l = p + 4 * k;
        if (l < L) {
            float4 e = emb4[(size_t)idx[l] * (D / 4) + lane];
            if (k & 1) { q1.x += e.x; q1.y += e.y; q1.z += e.z; q1.w += e.w; }
            else       { q0.x += e.x; q0.y += e.y; q0.z += e.z; q0.w += e.w; }
        }
    }
    #pragma unroll
    for (int k = 0; k < 25; k++) {
        int l = L + p + 4 * k;
        if (l < 3 * L) {
            float4 e = emb4[(size_t)idx[l] * (D / 4) + lane];
            if (k & 1) { s1.x += e.x; s1.y += e.y; s1.z += e.z; s1.w += e.w; }
            else       { s0.x += e.x; s0.y += e.y; s0.z += e.z; s0.w += e.w; }
        }
    }

    redq [p][lane] = make_float4(q0.x+q1.x, q0.y+q1.y, q0.z+q1.z, q0.w+q1.w);
    redsv[p][lane] = make_float4(s0.x+s1.x, s0.y+s1.y, s0.z+s1.z, s0.w+s1.w);
    __syncthreads();

    if (tid < 64) {
        float4 a = redq[0][tid], c = redq[1][tid], d = redq[2][tid], e = redq[3][tid];
        g_tq[b * (D / 4) + tid] =
            make_float4(a.x+c.x+d.x+e.x, a.y+c.y+d.y+e.y, a.z+c.z+d.z+e.z, a.w+c.w+d.w+e.w);
    } else if (tid < 128) {
        int ln = tid - 64;
        float4 a = redsv[0][ln], c = redsv[1][ln], d = redsv[2][ln], e = redsv[3][ln];
        g_tsv[b * (D / 4) + ln] =
            make_float4(a.x+c.x+d.x+e.x, a.y+c.y+d.y+e.y, a.z+c.z+d.z+e.z, a.w+c.w+d.w+e.w);
    }
}

// ------------- Kernel 2: fused tf32 mma (both matrices) + gate epilogue -----
// Block = 16 batches; grid 256. Warp w owns n-tiles w*4..w*4+3 for BOTH mats.
// Epilogue applies gates straight from C fragments: no g_gq/g_gs round trip.
__global__ void __launch_bounds__(256) mma_gate(
    const int*   __restrict__ slot_names,
    const float* __restrict__ emb,
    float*       __restrict__ out)
{
    __shared__ float tq_sm[16][260];   // +4 pad -> conflict-free A-frag LDS
    __shared__ float ts_sm[16][260];
    __shared__ int   sidx[64];

    const int tid = threadIdx.x;
    const int b0g = blockIdx.x * 16;

    // stage t_q / t_sv (16 x 256 fp32 each) into padded smem
    {
        #pragma unroll
        for (int e = tid; e < 16 * 64; e += 256) {
            int bb = e >> 6, c4 = e & 63;
            float4 vq = g_tq [(size_t)(b0g + bb) * 64 + c4];
            float4 vs = g_tsv[(size_t)(b0g + bb) * 64 + c4];
            tq_sm[bb][c4 * 4 + 0] = vq.x; tq_sm[bb][c4 * 4 + 1] = vq.y;
            tq_sm[bb][c4 * 4 + 2] = vq.z; tq_sm[bb][c4 * 4 + 3] = vq.w;
            ts_sm[bb][c4 * 4 + 0] = vs.x; ts_sm[bb][c4 * 4 + 1] = vs.y;
            ts_sm[bb][c4 * 4 + 2] = vs.z; ts_sm[bb][c4 * 4 + 3] = vs.w;
        }
    }
    if (tid < 64) sidx[tid] = slot_names[b0g * 4 + tid];
    __syncthreads();

    const int wid  = tid >> 5;
    const int lane = tid & 31;
    const int row  = lane >> 2;      // A-frag row group (batch)
    const int colb = lane & 3;       // A-frag col-in-group

    float c[2][4][4];                // [matrix][n-tile][frag]
    #pragma unroll
    for (int m = 0; m < 2; m++)
        #pragma unroll
        for (int n = 0; n < 4; n++)
            #pragma unroll
            for (int k = 0; k < 4; k++) c[m][n][k] = 0.f;

    #pragma unroll
    for (int kk = 0; kk < 32; kk++) {
        const int k8 = kk * 8;
        uint32_t aq0 = f2tf32(tq_sm[row    ][k8 + colb    ]);
        uint32_t aq1 = f2tf32(tq_sm[row + 8][k8 + colb    ]);
        uint32_t aq2 = f2tf32(tq_sm[row    ][k8 + colb + 4]);
        uint32_t aq3 = f2tf32(tq_sm[row + 8][k8 + colb + 4]);
        uint32_t as0 = f2tf32(ts_sm[row    ][k8 + colb    ]);
        uint32_t as1 = f2tf32(ts_sm[row + 8][k8 + colb    ]);
        uint32_t as2 = f2tf32(ts_sm[row    ][k8 + colb + 4]);
        uint32_t as3 = f2tf32(ts_sm[row + 8][k8 + colb + 4]);
        #pragma unroll
        for (int n = 0; n < 4; n++) {
            const int fi = (kk * 32 + (wid * 4 + n)) * 32 + lane;
            uint2 bq = g_wp1[fi];                    // coalesced LDG.64
            uint2 bs = g_wp2[fi];
            asm volatile(
                "mma.sync.aligned.m16n8k8.row.col.f32.tf32.tf32.f32 "
                "{%0,%1,%2,%3}, {%4,%5,%6,%7}, {%8,%9}, {%0,%1,%2,%3};"
                : "+f"(c[0][n][0]), "+f"(c[0][n][1]), "+f"(c[0][n][2]), "+f"(c[0][n][3])
                : "r"(aq0), "r"(aq1), "r"(aq2), "r"(aq3), "r"(bq.x), "r"(bq.y));
            asm volatile(
                "mma.sync.aligned.m16n8k8.row.col.f32.tf32.tf32.f32 "
                "{%0,%1,%2,%3}, {%4,%5,%6,%7}, {%8,%9}, {%0,%1,%2,%3};"
                : "+f"(c[1][n][0]), "+f"(c[1][n][1]), "+f"(c[1][n][2]), "+f"(c[1][n][3])
                : "r"(as0), "r"(as1), "r"(as2), "r"(as3), "r"(bs.x), "r"(bs.y));
        }
    }

    // gate epilogue straight from fragments:
    // frag k=0/1 -> (row, col, col+1); k=2/3 -> (row+8, col, col+1)
    #pragma unroll
    for (int n = 0; n < 4; n++) {
        const int col = (wid * 4 + n) * 8 + colb * 2;
        #pragma unroll
        for (int r2 = 0; r2 < 2; r2++) {
            const int brow = row + r2 * 8;
            const float gq0 = c[0][n][r2 * 2 + 0], gq1 = c[0][n][r2 * 2 + 1];
            const float gs0 = c[1][n][r2 * 2 + 0], gs1 = c[1][n][r2 * 2 + 1];
            #pragma unroll
            for (int sl = 0; sl < 4; sl++) {
                int erow = sidx[brow * 4 + sl];
                float2 cc = *(const float2*)&emb[(size_t)erow * D + col];
                float2 o;
                o.x = cc.x + fsigmoid(cc.x * gq0) + fsigmoid(cc.x * gs0);
                o.y = cc.y + fsigmoid(cc.y * gq1) + fsigmoid(cc.y * gs1);
                *(float2*)&out[((size_t)(b0g + brow) * 4 + sl) * D + col] = o;
            }
        }
    }
}

extern "C" void kernel_launch(void* const* d_in, const int* in_sizes, int n_in,
                              void* d_out, int out_size)
{
    const int*   acts_req   = (const int*)  d_in[0];
    const int*   acts_slot  = (const int*)  d_in[1];
    const int*   acts_val   = (const int*)  d_in[2];
    const int*   slot_names = (const int*)  d_in[3];
    const float* emb        = (const float*)d_in[4];
    const float* w1         = (const float*)d_in[5];
    const float* w2         = (const float*)d_in[6];
    float*       out        = (float*)d_out;

    gather_kernel<<<BSZ, 256>>>(acts_req, acts_slot, acts_val, w1, w2, emb);
    mma_gate<<<BSZ / 16, 256>>>(slot_names, emb, out);
}

// round 16
// speedup vs baseline: 1.1724x; 1.1724x over previous
#include <cuda_runtime.h>
#include <cstdint>

#define D       256
#define L       50
#define BSZ     4096

// Weights prepacked as tf32 B-fragments: uint2 at [(kk*32 + nt)*32 + lane]
//   .x = tf32(W[nt*8 + lane/4][kk*8 + lane%4])
//   .y = tf32(W[nt*8 + lane/4][kk*8 + lane%4 + 4])
__device__ uint2 g_wp1[32 * 32 * 32];   // 256 KB
__device__ uint2 g_wp2[32 * 32 * 32];
// Gather outputs: 64 float4 channels per batch (8 MB total)
__device__ float4 g_tq [BSZ * (D / 4)];
__device__ float4 g_tsv[BSZ * (D / 4)];
// Full GEMV results (4 MB each)
__device__ float g_gq[BSZ * D];
__device__ float g_gs[BSZ * D];

__device__ __forceinline__ float fsigmoid(float x) {
    return 1.0f / (1.0f + __expf(-x));
}

__device__ __forceinline__ uint32_t f2tf32(float f) {
    uint32_t u;
    asm("cvt.rna.tf32.f32 %0, %1;" : "=r"(u) : "f"(f));
    return u;
}

// ------------- Kernel 1: ragged gather-sum (one block/batch) + weight repack -
__global__ void __launch_bounds__(256, 8) gather_kernel(
    const int*   __restrict__ acts_req,
    const int*   __restrict__ acts_slot,
    const int*   __restrict__ acts_val,
    const float* __restrict__ w1,
    const float* __restrict__ w2,
    const float* __restrict__ emb)
{
    __shared__ int idx[3 * L + 2];
    __shared__ __align__(16) float4 redq [4][D / 4];
    __shared__ __align__(16) float4 redsv[4][D / 4];

    const int b   = blockIdx.x;
    const int tid = threadIdx.x;

    // Fold weight repack+tf32 fragment packing into the first 256 blocks.
    // 256 blocks x 256 threads = 65536 = 2 matrices x 32kk x 32nt x 32 lanes.
    if (b < 256) {
        int id   = b * 256 + tid;
        int mtx  = id >> 15;
        int r    = id & 32767;
        int kk   = r >> 10;
        int nt   = (r >> 5) & 31;
        int lane = r & 31;
        int i = nt * 8 + (lane >> 2);
        int j = kk * 8 + (lane & 3);
        const float* w = mtx ? w2 : w1;
        uint2 frag;
        frag.x = f2tf32(w[i * D + j]);
        frag.y = f2tf32(w[i * D + j + 4]);
        (mtx ? g_wp2 : g_wp1)[(kk * 32 + nt) * 32 + lane] = frag;
    }

    if (tid < 3 * L) {
        int v;
        if      (tid < L)     v = acts_req [b * L + tid];
        else if (tid < 2 * L) v = acts_slot[b * L + (tid - L)];
        else                  v = acts_val [b * L + (tid - 2 * L)];
        idx[tid] = v;
    }
    __syncthreads();

    const float4* __restrict__ emb4 = (const float4*)emb;
    const int p    = tid >> 6;
    const int lane = tid & 63;

    float4 q0 = make_float4(0.f,0.f,0.f,0.f), q1 = q0, s0 = q0, s1 = q0;

    #pragma unroll
    for (int k = 0; k < 13; k++) {
        int l = p + 4 * k;
        if (l < L) {
            float4 e = emb4[(size_t)idx[l] * (D / 4) + lane];
            if (k & 1) { q1.x += e.x; q1.y += e.y; q1.z += e.z; q1.w += e.w; }
            else       { q0.x += e.x; q0.y += e.y; q0.z += e.z; q0.w += e.w; }
        }
    }
    #pragma unroll
    for (int k = 0; k < 25; k++) {
        int l = L + p + 4 * k;
        if (l < 3 * L) {
            float4 e = emb4[(size_t)idx[l] * (D / 4) + lane];
            if (k & 1) { s1.x += e.x; s1.y += e.y; s1.z += e.z; s1.w += e.w; }
            else       { s0.x += e.x; s0.y += e.y; s0.z += e.z; s0.w += e.w; }
        }
    }

    redq [p][lane] = make_float4(q0.x+q1.x, q0.y+q1.y, q0.z+q1.z, q0.w+q1.w);
    redsv[p][lane] = make_float4(s0.x+s1.x, s0.y+s1.y, s0.z+s1.z, s0.w+s1.w);
    __syncthreads();

    if (tid < 64) {
        float4 a = redq[0][tid], c = redq[1][tid], d = redq[2][tid], e = redq[3][tid];
        g_tq[b * (D / 4) + tid] =
            make_float4(a.x+c.x+d.x+e.x, a.y+c.y+d.y+e.y, a.z+c.z+d.z+e.z, a.w+c.w+d.w+e.w);
    } else if (tid < 128) {
        int ln = tid - 64;
        float4 a = redsv[0][ln], c = redsv[1][ln], d = redsv[2][ln], e = redsv[3][ln];
        g_tsv[b * (D / 4) + ln] =
            make_float4(a.x+c.x+d.x+e.x, a.y+c.y+d.y+e.y, a.z+c.z+d.z+e.z, a.w+c.w+d.w+e.w);
    }
}

// ------------- Kernel 2: tf32 mma GEMV, n-split x2 --------------------------
// Block = (16-batch group) x (matrix m) x (n-half h). Grid = 256*2*2 = 1024.
// Warp w owns n-tiles h*16 + w*2 .. +1. Weight traffic unchanged, occupancy 2x.
__global__ void __launch_bounds__(256) mma_gemm(void)
{
    __shared__ float t_sm[16][260];   // +4 pad -> A-frag LDS conflict-free

    const int tid = threadIdx.x;
    const int m   = blockIdx.x & 1;          // 0: w1/tq -> gq, 1: w2/tsv -> gs
    const int h   = (blockIdx.x >> 1) & 1;   // n-half
    const int b0g = (blockIdx.x >> 2) * 16;

    // stage t (16 x 256 fp32) into padded smem
    {
        const float4* tsrc = m ? (const float4*)g_tsv : (const float4*)g_tq;
        #pragma unroll
        for (int e = tid; e < 16 * 64; e += 256) {
            int bb = e >> 6, c4 = e & 63;
            float4 v = tsrc[(size_t)(b0g + bb) * 64 + c4];
            t_sm[bb][c4 * 4 + 0] = v.x;
            t_sm[bb][c4 * 4 + 1] = v.y;
            t_sm[bb][c4 * 4 + 2] = v.z;
            t_sm[bb][c4 * 4 + 3] = v.w;
        }
    }
    __syncthreads();

    const int wid  = tid >> 5;
    const int lane = tid & 31;
    const int row  = lane >> 2;      // A-frag row group (batch)
    const int colb = lane & 3;       // A-frag col-in-group
    const int nt0  = h * 16 + wid * 2;   // first of this warp's 2 n-tiles

    float c[2][4];
    #pragma unroll
    for (int n = 0; n < 2; n++)
        #pragma unroll
        for (int k = 0; k < 4; k++) c[n][k] = 0.f;

    const uint2* __restrict__ wp = m ? g_wp2 : g_wp1;

    #pragma unroll
    for (int kk = 0; kk < 32; kk++) {
        const int k8 = kk * 8;
        uint32_t a0 = f2tf32(t_sm[row    ][k8 + colb    ]);
        uint32_t a1 = f2tf32(t_sm[row + 8][k8 + colb    ]);
        uint32_t a2 = f2tf32(t_sm[row    ][k8 + colb + 4]);
        uint32_t a3 = f2tf32(t_sm[row + 8][k8 + colb + 4]);
        uint2 bb[2];
        #pragma unroll
        for (int n = 0; n < 2; n++)
            bb[n] = wp[(kk * 32 + (nt0 + n)) * 32 + lane]; // coalesced LDG.64
        #pragma unroll
        for (int n = 0; n < 2; n++) {
            asm volatile(
                "mma.sync.aligned.m16n8k8.row.col.f32.tf32.tf32.f32 "
                "{%0,%1,%2,%3}, {%4,%5,%6,%7}, {%8,%9}, {%0,%1,%2,%3};"
                : "+f"(c[n][0]), "+f"(c[n][1]), "+f"(c[n][2]), "+f"(c[n][3])
                : "r"(a0), "r"(a1), "r"(a2), "r"(a3), "r"(bb[n].x), "r"(bb[n].y));
        }
    }

    // store C fragments: c0/c1 -> (row, col..col+1), c2/c3 -> (row+8, ...)
    float* __restrict__ gout = m ? g_gs : g_gq;
    #pragma unroll
    for (int n = 0; n < 2; n++) {
        int col = (nt0 + n) * 8 + colb * 2;
        *(float2*)&gout[(size_t)(b0g + row    ) * D + col] = make_float2(c[n][0], c[n][1]);
        *(float2*)&gout[(size_t)(b0g + row + 8) * D + col] = make_float2(c[n][2], c[n][3]);
    }
}

// ------------- Kernel 3: gate epilogue, 1024 blocks -------------------------
// Block = 4 batches x 64 channel-groups (float4 per thread).
__global__ void __launch_bounds__(256) gate_kernel(
    const int*   __restrict__ slot_names,
    const float* __restrict__ emb,
    float*       __restrict__ out)
{
    __shared__ int sidx[16];

    const int tid = threadIdx.x;
    const int b0  = blockIdx.x * 4;

    if (tid < 16) sidx[tid] = slot_names[b0 * 4 + tid];
    __syncthreads();

    const int tb = tid >> 6;         // batch within block
    const int tc = tid & 63;         // float4 channel group
    const int b  = b0 + tb;

    const float4 gq = ((const float4*)g_gq)[(size_t)b * (D / 4) + tc];
    const float4 gs = ((const float4*)g_gs)[(size_t)b * (D / 4) + tc];

    const float4* __restrict__ emb4 = (const float4*)emb;
    float4* __restrict__ out4 = (float4*)out;
    #pragma unroll
    for (int sl = 0; sl < 4; sl++) {
        int row = sidx[tb * 4 + sl];
        float4 c = emb4[(size_t)row * (D / 4) + tc];
        float4 o;
        o.x = c.x + fsigmoid(c.x * gq.x) + fsigmoid(c.x * gs.x);
        o.y = c.y + fsigmoid(c.y * gq.y) + fsigmoid(c.y * gs.y);
        o.z = c.z + fsigmoid(c.z * gq.z) + fsigmoid(c.z * gs.z);
        o.w = c.w + fsigmoid(c.w * gq.w) + fsigmoid(c.w * gs.w);
        out4[((size_t)b * 4 + sl) * (D / 4) + tc] = o;
    }
}

extern "C" void kernel_launch(void* const* d_in, const int* in_sizes, int n_in,
                              void* d_out, int out_size)
{
    const int*   acts_req   = (const int*)  d_in[0];
    const int*   acts_slot  = (const int*)  d_in[1];
    const int*   acts_val   = (const int*)  d_in[2];
    const int*   slot_names = (const int*)  d_in[3];
    const float* emb        = (const float*)d_in[4];
    const float* w1         = (const float*)d_in[5];
    const float* w2         = (const float*)d_in[6];
    float*       out        = (float*)d_out;

    gather_kernel<<<BSZ, 256>>>(acts_req, acts_slot, acts_val, w1, w2, emb);
    mma_gemm<<<(BSZ / 16) * 4, 256>>>();
    gate_kernel<<<BSZ / 4, 256>>>(slot_names, emb, out);
}